// round 5
// baseline (speedup 1.0000x reference)
#include <cuda_runtime.h>

#define NN 16384
#define DEG 20
typedef unsigned long long u64;

__device__ float g_qt[NN * 32];

static __device__ __forceinline__ u64 pk2(float lo, float hi) {
    u64 r; asm("mov.b64 %0, {%1, %2};" : "=l"(r) : "f"(lo), "f"(hi)); return r;
}
static __device__ __forceinline__ void upk2(u64 v, float& lo, float& hi) {
    asm("mov.b64 {%0, %1}, %2;" : "=f"(lo), "=f"(hi) : "l"(v));
}
static __device__ __forceinline__ u64 f2(u64 a, u64 b, u64 c) {
    u64 d; asm("fma.rn.f32x2 %0, %1, %2, %3;" : "=l"(d) : "l"(a), "l"(b), "l"(c)); return d;
}
static __device__ __forceinline__ float ss(float x) {
    return x > 0.f ? __expf(__fdividef(-1.f, x)) : 0.f;
}
static __device__ __forceinline__ float bsum(float v) {
#pragma unroll
    for (int o = 16; o >= 1; o >>= 1) v += __shfl_xor_sync(0xffffffffu, v, o);
    return v;
}

// ---------------- K0: fold Wq@Wd/sqrt(8) into per-node query ----------------
__global__ void k0_qt(const float* __restrict__ f, const float* __restrict__ Wq_s,
                      const float* __restrict__ Wq_v, const float* __restrict__ Wd_s,
                      const float* __restrict__ Wd_v) {
    __shared__ float As[64], Av[64];
    int t = threadIdx.x;
    if (t < 64) {
        int m = t >> 3, j = t & 7;
        float s = 0.f, v = 0.f;
#pragma unroll
        for (int o = 0; o < 8; o++) {
            s = fmaf(Wq_s[m * 8 + o], Wd_s[o * 8 + j], s);
            v = fmaf(Wq_v[m * 8 + o], Wd_v[o * 8 + j], v);
        }
        As[t] = s * 0.35355339059327373f;
        Av[t] = v * 0.35355339059327373f;
    }
    __syncthreads();
    int n = blockIdx.x * 256 + t;
    float fs[8], fv[24];
#pragma unroll
    for (int m = 0; m < 8; m++) fs[m] = f[n * 32 + m];
#pragma unroll
    for (int m = 0; m < 24; m++) fv[m] = f[n * 32 + 8 + m];
#pragma unroll
    for (int j = 0; j < 8; j++) {
        float s = 0.f;
#pragma unroll
        for (int m = 0; m < 8; m++) s = fmaf(fs[m], As[m * 8 + j], s);
        g_qt[n * 32 + j] = s;
    }
#pragma unroll
    for (int j = 0; j < 8; j++) {
        float v0 = 0.f, v1 = 0.f, v2 = 0.f;
#pragma unroll
        for (int m = 0; m < 8; m++) {
            float a = Av[m * 8 + j];
            v0 = fmaf(fv[m * 3 + 0], a, v0);
            v1 = fmaf(fv[m * 3 + 1], a, v1);
            v2 = fmaf(fv[m * 3 + 2], a, v2);
        }
        g_qt[n * 32 + 8 + j * 3 + 0] = v0;
        g_qt[n * 32 + 8 + j * 3 + 1] = v1;
        g_qt[n * 32 + 8 + j * 3 + 2] = v2;
    }
}

// ---------------- main: 1 warp per node, 10-edge FC2 sweeps ----------------
// smem: W2[16384] W1[640] then 12 warp-scratch regions of 1920 floats
#define SM_W1 16384
#define SM_NS 17024
#define NS_STR 1920
#define NS_H   0      // [64][12]  (current sweep's h, e-local 0..9)
#define NS_GS  768    // [20][8]
#define NS_GD  928    // [20][8]
#define NS_GV  1088   // [20][8][3]
#define NS_U   1568   // [20][3]
#define NS_EMB 1632   // [20][10]
#define NS_LC  1832   // [20]
#define NS_LG  1856   // [20]
#define NS_CO  1880   // [20]
#define SMEM_BYTES ((SM_NS + 12 * NS_STR) * 4)

static __device__ __forceinline__ void stage(float* sm, const float* W2,
                                             const float* W1, int tid) {
    float4* d = (float4*)sm;
    const float4* s2 = (const float4*)W2;
    const float4* s1 = (const float4*)W1;
    for (int i = tid; i < 4096; i += 384) d[i] = s2[i];
    for (int i = tid; i < 160; i += 384) d[4096 + i] = s1[i];
}

__global__ __launch_bounds__(384, 1) void se3_main(
    const float* __restrict__ f, const float* __restrict__ pos,
    const float* __restrict__ Wk1, const float* __restrict__ Wk2,
    const float* __restrict__ Wv1, const float* __restrict__ Wv2,
    const int* __restrict__ edge_src, float* __restrict__ out) {
    extern __shared__ float sm[];
    const int tid = threadIdx.x;
    const int wid = tid >> 5, lane = tid & 31;
    const int n = blockIdx.x * 12 + wid;
    const bool active = (n < NN);
    float* ws = sm + SM_NS + wid * NS_STR;

    // ---- edge setup: one warp = all 20 edges of its node ----
    if (active) {
        const float px = pos[n * 3 + 0], py = pos[n * 3 + 1], pz = pos[n * 3 + 2];
#pragma unroll 4
        for (int e = 0; e < 20; e++) {
            int src = edge_src[n * DEG + e];
            float dx = pos[src * 3 + 0] - px;
            float dy = pos[src * 3 + 1] - py;
            float dz = pos[src * 3 + 2] - pz;
            float r2 = fmaf(dx, dx, fmaf(dy, dy, dz * dz));
            float ir = rsqrtf(r2);
            float r = r2 * ir;
            float u0 = dx * ir, u1 = dy * ir, u2 = dz * ir;
            if (lane < 8) {
                int i = lane;
                float gsv = f[src * 32 + i];
                float a0 = f[src * 32 + 8 + 3 * i + 0];
                float a1 = f[src * 32 + 8 + 3 * i + 1];
                float a2 = f[src * 32 + 8 + 3 * i + 2];
                ws[NS_GS + e * 8 + i] = gsv;
                ws[NS_GV + e * 24 + i * 3 + 0] = a0;
                ws[NS_GV + e * 24 + i * 3 + 1] = a1;
                ws[NS_GV + e * 24 + i * 3 + 2] = a2;
                ws[NS_GD + e * 8 + i] = fmaf(a0, u0, fmaf(a1, u1, a2 * u2));
            } else if (lane < 18) {
                int b = lane - 8;
                float rr = r * (11.0f / 3.5f);
                float d = rr - (float)(b + 1);
                ws[NS_EMB + e * 10 + b] = 26.66929f * ss(d + 1.f) * ss(1.f - d);
            } else if (lane == 18) {
                ws[NS_U + e * 3 + 0] = u0;
                ws[NS_U + e * 3 + 1] = u1;
                ws[NS_U + e * 3 + 2] = u2;
                float x = 10.f * (1.f - r * (1.f / 3.5f));
                ws[NS_LC + e] = (x > 0.f) ? -__fdividef(1.f, x) : -1e30f;
            }
        }
    }
    stage(sm, Wk2, Wk1, tid);
    __syncthreads();

    const int pr = lane >> 4, ii = (lane >> 1) & 7, jh = lane & 1;
    float qts[4], qtv[4][3];
    if (active) {
#pragma unroll
        for (int k = 0; k < 4; k++) {
            qts[k] = g_qt[n * 32 + jh * 4 + k];
#pragma unroll
            for (int c = 0; c < 3; c++)
                qtv[k][c] = g_qt[n * 32 + 8 + (jh * 4 + k) * 3 + c];
        }
    }

    float outs[4] = {0.f, 0.f, 0.f, 0.f};
    float outv[4][3] = {};

#pragma unroll 1
    for (int pass = 0; pass < 2; pass++) {
        if (pass == 1) {
            __syncthreads();
            stage(sm, Wv2, Wv1, tid);
            __syncthreads();
        }
        if (active) {
#pragma unroll 1
            for (int s = 0; s < 2; s++) {
                // ---- FC1: lane computes t = lane, lane+32 for this sweep ----
                {
                    const float* W1s = sm + SM_W1;
                    float wc0[10], wc1[10];
#pragma unroll
                    for (int b = 0; b < 10; b++) {
                        wc0[b] = W1s[b * 64 + lane];
                        wc1[b] = W1s[b * 64 + 32 + lane];
                    }
#pragma unroll
                    for (int el = 0; el < 10; el++) {
                        int e = s * 10 + el;
                        float a0 = 0.f, a1 = 0.f;
#pragma unroll
                        for (int b = 0; b < 10; b++) {
                            float em = ws[NS_EMB + e * 10 + b];
                            a0 = fmaf(em, wc0[b], a0);
                            a1 = fmaf(em, wc1[b], a1);
                        }
                        a0 *= 0.31622776601683794f;
                        a1 *= 0.31622776601683794f;
                        ws[NS_H + lane * 12 + el] =
                            __fdividef(a0, 1.f + __expf(-a0)) * 0.125f;
                        ws[NS_H + (lane + 32) * 12 + el] =
                            __fdividef(a1, 1.f + __expf(-a1)) * 0.125f;
                    }
                }
                __syncwarp();

                // ---- FC2: 10 edges, edge-packed f32x2; lane owns 8 flat outs ----
                u64 accA[4][5], accB[4][5];
#pragma unroll
                for (int k = 0; k < 4; k++)
#pragma unroll
                    for (int p = 0; p < 5; p++) { accA[k][p] = 0ULL; accB[k][p] = 0ULL; }
                {
                    const float4* w4 = (const float4*)sm;
                    const float* hb = ws + NS_H;
#pragma unroll 4
                    for (int t = 0; t < 64; t++) {
                        float4 wA = w4[t * 64 + lane];
                        float4 wB = w4[t * 64 + 32 + lane];
                        ulonglong2 h01 = *(const ulonglong2*)(hb + t * 12);
                        ulonglong2 h23 = *(const ulonglong2*)(hb + t * 12 + 4);
                        u64 h4 = *(const u64*)(hb + t * 12 + 8);
                        u64 wa[4] = {pk2(wA.x, wA.x), pk2(wA.y, wA.y),
                                     pk2(wA.z, wA.z), pk2(wA.w, wA.w)};
                        u64 wb[4] = {pk2(wB.x, wB.x), pk2(wB.y, wB.y),
                                     pk2(wB.z, wB.z), pk2(wB.w, wB.w)};
                        u64 hh[5] = {h01.x, h01.y, h23.x, h23.y, h4};
#pragma unroll
                        for (int k = 0; k < 4; k++)
#pragma unroll
                            for (int p = 0; p < 5; p++) {
                                accA[k][p] = f2(wa[k], hh[p], accA[k][p]);
                                accB[k][p] = f2(wb[k], hh[p], accB[k][p]);
                            }
                    }
                }

                if (pass == 0) {
                    // ---- logits ----
                    float mine = 0.f;
#pragma unroll
                    for (int p = 0; p < 5; p++) {
                        float vA0[4], vA1[4], vB0[4], vB1[4];
#pragma unroll
                        for (int k = 0; k < 4; k++) {
                            upk2(accA[k][p], vA0[k], vA1[k]);
                            upk2(accB[k][p], vB0[k], vB1[k]);
                        }
                        int e0 = s * 10 + 2 * p, e1 = e0 + 1;
                        float part0, part1;
#pragma unroll
                        for (int h = 0; h < 2; h++) {
                            int e = h ? e1 : e0;
                            float* vA = h ? vA1 : vA0;
                            float* vB = h ? vB1 : vB0;
                            float gse = ws[NS_GS + e * 8 + ii];
                            float sA = pr ? ws[NS_GD + e * 8 + ii] : gse;
                            float dA = fmaf(vA[0], qts[0], fmaf(vA[1], qts[1],
                                        fmaf(vA[2], qts[2], vA[3] * qts[3])));
                            float part = sA * dA;
                            if (pr == 0) {
                                float u0 = ws[NS_U + e * 3 + 0];
                                float u1 = ws[NS_U + e * 3 + 1];
                                float u2 = ws[NS_U + e * 3 + 2];
                                float sum = 0.f;
#pragma unroll
                                for (int k = 0; k < 4; k++) {
                                    float qdu = fmaf(qtv[k][0], u0,
                                                fmaf(qtv[k][1], u1, qtv[k][2] * u2));
                                    sum = fmaf(qdu, vB[k], sum);
                                }
                                part = fmaf(gse, sum, part);
                            } else {
                                float g0 = ws[NS_GV + e * 24 + ii * 3 + 0];
                                float g1 = ws[NS_GV + e * 24 + ii * 3 + 1];
                                float g2 = ws[NS_GV + e * 24 + ii * 3 + 2];
                                float sum = 0.f;
#pragma unroll
                                for (int k = 0; k < 4; k++) {
                                    float cc = fmaf(qtv[k][0], g0,
                                               fmaf(qtv[k][1], g1, qtv[k][2] * g2));
                                    sum = fmaf(cc, vB[k], sum);
                                }
                                part = fmaf(0.5773502691896258f, sum, part);
                            }
                            if (h) part1 = part; else part0 = part;
                        }
                        part0 = bsum(part0);
                        part1 = bsum(part1);
                        if (lane == 2 * p) mine = part0;
                        if (lane == 2 * p + 1) mine = part1;
                    }
                    if (lane < 10) ws[NS_LG + s * 10 + lane] = mine;
                } else {
                    // ---- v-side accumulation ----
#pragma unroll
                    for (int p = 0; p < 5; p++) {
                        float vA0[4], vA1[4], vB0[4], vB1[4];
#pragma unroll
                        for (int k = 0; k < 4; k++) {
                            upk2(accA[k][p], vA0[k], vA1[k]);
                            upk2(accB[k][p], vB0[k], vB1[k]);
                        }
                        int e0 = s * 10 + 2 * p, e1 = e0 + 1;
#pragma unroll
                        for (int h = 0; h < 2; h++) {
                            int e = h ? e1 : e0;
                            float* vA = h ? vA1 : vA0;
                            float* vB = h ? vB1 : vB0;
                            float c = ws[NS_CO + e];
                            float gse = ws[NS_GS + e * 8 + ii];
                            float sA = c * (pr ? ws[NS_GD + e * 8 + ii] : gse);
#pragma unroll
                            for (int k = 0; k < 4; k++) outs[k] = fmaf(sA, vA[k], outs[k]);
                            if (pr == 0) {
                                float b0 = c * 1.7320508075688772f * gse;
                                float t0 = b0 * ws[NS_U + e * 3 + 0];
                                float t1 = b0 * ws[NS_U + e * 3 + 1];
                                float t2 = b0 * ws[NS_U + e * 3 + 2];
#pragma unroll
                                for (int k = 0; k < 4; k++) {
                                    outv[k][0] = fmaf(t0, vB[k], outv[k][0]);
                                    outv[k][1] = fmaf(t1, vB[k], outv[k][1]);
                                    outv[k][2] = fmaf(t2, vB[k], outv[k][2]);
                                }
                            } else {
                                float g0 = c * ws[NS_GV + e * 24 + ii * 3 + 0];
                                float g1 = c * ws[NS_GV + e * 24 + ii * 3 + 1];
                                float g2 = c * ws[NS_GV + e * 24 + ii * 3 + 2];
#pragma unroll
                                for (int k = 0; k < 4; k++) {
                                    outv[k][0] = fmaf(g0, vB[k], outv[k][0]);
                                    outv[k][1] = fmaf(g1, vB[k], outv[k][1]);
                                    outv[k][2] = fmaf(g2, vB[k], outv[k][2]);
                                }
                            }
                        }
                    }
                }
                __syncwarp();
            }  // sweep

            if (pass == 0) {
                // in-warp softmax over 20 edges; coef folds 0.25 tp norm
                float L = -3.0e38f;
                if (lane < 20)
                    L = fmaf(0.022097086912079608f, ws[NS_LG + lane], ws[NS_LC + lane]);
                float M = L;
#pragma unroll
                for (int o = 16; o >= 1; o >>= 1)
                    M = fmaxf(M, __shfl_xor_sync(0xffffffffu, M, o));
                float ex = (lane < 20) ? __expf(L - M) : 0.f;
                float z = bsum(ex);
                if (lane < 20)
                    ws[NS_CO + lane] = 0.25f * sqrtf(__fdividef(ex, z) + 1e-12f);
                __syncwarp();
            }
        }  // active
    }  // pass

    // ---- warp output reduction: xor16 merges path pairs, xor8/4/2 sum over ii ----
    if (active) {
#pragma unroll
        for (int o = 16; o >= 2; o >>= 1) {
#pragma unroll
            for (int k = 0; k < 4; k++) {
                outs[k] += __shfl_xor_sync(0xffffffffu, outs[k], o);
#pragma unroll
                for (int c = 0; c < 3; c++)
                    outv[k][c] += __shfl_xor_sync(0xffffffffu, outv[k][c], o);
            }
        }
        if (lane < 2) {
            int o0 = lane * 4;
#pragma unroll
            for (int k = 0; k < 4; k++) {
                out[n * 32 + o0 + k] = outs[k];
#pragma unroll
                for (int c = 0; c < 3; c++)
                    out[n * 32 + 8 + (o0 + k) * 3 + c] = outv[k][c];
            }
        }
    }
}

extern "C" void kernel_launch(void* const* d_in, const int* in_sizes, int n_in,
                              void* d_out, int out_size) {
    const float* f    = (const float*)d_in[0];
    const float* pos  = (const float*)d_in[1];
    const float* Wq_s = (const float*)d_in[2];
    const float* Wq_v = (const float*)d_in[3];
    const float* Wk1  = (const float*)d_in[4];
    const float* Wk2  = (const float*)d_in[5];
    const float* Wv1  = (const float*)d_in[6];
    const float* Wv2  = (const float*)d_in[7];
    const float* Wd_s = (const float*)d_in[8];
    const float* Wd_v = (const float*)d_in[9];
    const int* esrc   = (const int*)d_in[10];
    float* out = (float*)d_out;

    cudaFuncSetAttribute(se3_main, cudaFuncAttributeMaxDynamicSharedMemorySize, SMEM_BYTES);
    k0_qt<<<64, 256>>>(f, Wq_s, Wq_v, Wd_s, Wd_v);
    se3_main<<<(NN + 11) / 12, 384, SMEM_BYTES>>>(f, pos, Wk1, Wk2, Wv1, Wv2, esrc, out);
}

// round 6
// speedup vs baseline: 1.7872x; 1.7872x over previous
#include <cuda_runtime.h>

#define NN 16384
#define DEG 20
typedef unsigned long long u64;

__device__ float g_qt[NN * 32];

static __device__ __forceinline__ u64 pk2(float lo, float hi) {
    u64 r; asm("mov.b64 %0, {%1, %2};" : "=l"(r) : "f"(lo), "f"(hi)); return r;
}
static __device__ __forceinline__ void upk2(u64 v, float& lo, float& hi) {
    asm("mov.b64 {%0, %1}, %2;" : "=f"(lo), "=f"(hi) : "l"(v));
}
static __device__ __forceinline__ u64 f2(u64 a, u64 b, u64 c) {
    u64 d; asm("fma.rn.f32x2 %0, %1, %2, %3;" : "=l"(d) : "l"(a), "l"(b), "l"(c)); return d;
}
static __device__ __forceinline__ u64 mul2(u64 a, u64 b) {
    u64 d; asm("mul.rn.f32x2 %0, %1, %2;" : "=l"(d) : "l"(a), "l"(b)); return d;
}
static __device__ __forceinline__ u64 add2(u64 a, u64 b) {
    u64 d; asm("add.rn.f32x2 %0, %1, %2;" : "=l"(d) : "l"(a), "l"(b)); return d;
}
static __device__ __forceinline__ float ss(float x) {
    return x > 0.f ? __expf(__fdividef(-1.f, x)) : 0.f;
}
static __device__ __forceinline__ float bsum(float v) {
#pragma unroll
    for (int o = 16; o >= 1; o >>= 1) v += __shfl_xor_sync(0xffffffffu, v, o);
    return v;
}

// ---------------- K0: fold Wq@Wd/sqrt(8) into per-node query ----------------
__global__ void k0_qt(const float* __restrict__ f, const float* __restrict__ Wq_s,
                      const float* __restrict__ Wq_v, const float* __restrict__ Wd_s,
                      const float* __restrict__ Wd_v) {
    __shared__ float As[64], Av[64];
    int t = threadIdx.x;
    if (t < 64) {
        int m = t >> 3, j = t & 7;
        float s = 0.f, v = 0.f;
#pragma unroll
        for (int o = 0; o < 8; o++) {
            s = fmaf(Wq_s[m * 8 + o], Wd_s[o * 8 + j], s);
            v = fmaf(Wq_v[m * 8 + o], Wd_v[o * 8 + j], v);
        }
        As[t] = s * 0.35355339059327373f;
        Av[t] = v * 0.35355339059327373f;
    }
    __syncthreads();
    int n = blockIdx.x * 256 + t;
    float fs[8], fv[24];
#pragma unroll
    for (int m = 0; m < 8; m++) fs[m] = f[n * 32 + m];
#pragma unroll
    for (int m = 0; m < 24; m++) fv[m] = f[n * 32 + 8 + m];
#pragma unroll
    for (int j = 0; j < 8; j++) {
        float s = 0.f;
#pragma unroll
        for (int m = 0; m < 8; m++) s = fmaf(fs[m], As[m * 8 + j], s);
        g_qt[n * 32 + j] = s;
    }
#pragma unroll
    for (int j = 0; j < 8; j++) {
        float v0 = 0.f, v1 = 0.f, v2 = 0.f;
#pragma unroll
        for (int m = 0; m < 8; m++) {
            float a = Av[m * 8 + j];
            v0 = fmaf(fv[m * 3 + 0], a, v0);
            v1 = fmaf(fv[m * 3 + 1], a, v1);
            v2 = fmaf(fv[m * 3 + 2], a, v2);
        }
        g_qt[n * 32 + 8 + j * 3 + 0] = v0;
        g_qt[n * 32 + 8 + j * 3 + 1] = v1;
        g_qt[n * 32 + 8 + j * 3 + 2] = v2;
    }
}

// smem: W2 as u64 [64][129] (16512 fl) | W1 640 fl | 12 node scratch
#define SM_W1 16512
#define SM_NS 17152
#define NS_STR 1840
#define F_OFF   0     // [64][24] rows: gs(0-7) gd(8-15) su(16-39) gv(40-63)
#define EMB_OFF 1536  // [10][24]
#define LC_OFF  1776
#define LG_OFF  1796
#define CO_OFF  1816
#define SMEM_BYTES ((SM_NS + 12 * NS_STR) * 4)

static __device__ __forceinline__ void stage(float* sm, const float* W2,
                                             const float* W1, int tid) {
    u64* d = (u64*)sm;
    const u64* s = (const u64*)W2;
    for (int idx = tid; idx < 8192; idx += 384)
        d[(idx >> 7) * 129 + (idx & 127)] = s[idx];
    float* w1d = sm + SM_W1;
    for (int i = tid; i < 640; i += 384) w1d[i] = W1[i];
}

// h pairs over 20 edges for hidden unit t (folds /sqrt(10), silu, /8)
static __device__ __forceinline__ void fc1_row(const float* ws, const float* W1s,
                                               int t, u64* h) {
    u64 acc[10];
    {
        float w = W1s[t];
        u64 wd = pk2(w, w);
        const ulonglong2* Er = (const ulonglong2*)(ws + EMB_OFF);
#pragma unroll
        for (int m = 0; m < 5; m++) {
            ulonglong2 p = Er[m];
            acc[2 * m] = mul2(wd, p.x);
            acc[2 * m + 1] = mul2(wd, p.y);
        }
    }
#pragma unroll 1
    for (int b = 1; b < 10; b++) {
        float w = W1s[b * 64 + t];
        u64 wd = pk2(w, w);
        const ulonglong2* Er = (const ulonglong2*)(ws + EMB_OFF + b * 24);
#pragma unroll
        for (int m = 0; m < 5; m++) {
            ulonglong2 p = Er[m];
            acc[2 * m] = f2(wd, p.x, acc[2 * m]);
            acc[2 * m + 1] = f2(wd, p.y, acc[2 * m + 1]);
        }
    }
#pragma unroll
    for (int m = 0; m < 10; m++) {
        float a0, a1;
        upk2(acc[m], a0, a1);
        a0 *= 0.31622776601683794f;
        a1 *= 0.31622776601683794f;
        h[m] = pk2(__fdividef(a0, 1.f + __expf(-a0)) * 0.125f,
                   __fdividef(a1, 1.f + __expf(-a1)) * 0.125f);
    }
}

static __device__ __forceinline__ void dupd(const float* ws, int xi, float M, u64* D) {
    u64 Md = pk2(M, M);
    const ulonglong2* Fr = (const ulonglong2*)(ws + F_OFF + xi * 24);
#pragma unroll
    for (int m = 0; m < 5; m++) {
        ulonglong2 p = Fr[m];
        D[2 * m] = f2(Md, p.x, D[2 * m]);
        D[2 * m + 1] = f2(Md, p.y, D[2 * m + 1]);
    }
}

static __device__ __forceinline__ float srow(const float* ws, int xi, const u64* hp) {
    const ulonglong2* Fr = (const ulonglong2*)(ws + F_OFF + xi * 24);
    u64 s0 = 0ULL, s1 = 0ULL;
#pragma unroll
    for (int m = 0; m < 5; m++) {
        ulonglong2 p = Fr[m];
        s0 = f2(hp[2 * m], p.x, s0);
        s1 = f2(hp[2 * m + 1], p.y, s1);
    }
    float lo, hi;
    upk2(add2(s0, s1), lo, hi);
    return lo + hi;
}

static __device__ __forceinline__ float dot8(const u64* wk, const u64* q) {
    u64 p0 = mul2(wk[0], q[0]);
    p0 = f2(wk[1], q[1], p0);
    u64 p1 = mul2(wk[2], q[2]);
    p1 = f2(wk[3], q[3], p1);
    float lo, hi;
    upk2(add2(p0, p1), lo, hi);
    return lo + hi;
}

__global__ __launch_bounds__(384, 1) void se3_main(
    const float* __restrict__ f, const float* __restrict__ pos,
    const float* __restrict__ Wk1, const float* __restrict__ Wk2,
    const float* __restrict__ Wv1, const float* __restrict__ Wv2,
    const int* __restrict__ edge_src, float* __restrict__ out) {
    extern __shared__ float sm[];
    const int tid = threadIdx.x;
    const int wid = tid >> 5, lane = tid & 31;
    const int n = blockIdx.x * 12 + wid;
    const bool active = (n < NN);
    float* ws = sm + SM_NS + wid * NS_STR;
    const u64* W2s64 = (const u64*)sm;
    const float* W1s = sm + SM_W1;

    // ---- edge setup: lane e handles edge e ----
    if (active && lane < 20) {
        int e = lane;
        int src = edge_src[n * DEG + e];
        float dx = pos[src * 3 + 0] - pos[n * 3 + 0];
        float dy = pos[src * 3 + 1] - pos[n * 3 + 1];
        float dz = pos[src * 3 + 2] - pos[n * 3 + 2];
        float r2 = fmaf(dx, dx, fmaf(dy, dy, dz * dz));
        float ir = rsqrtf(r2);
        float r = r2 * ir;
        float uu[3] = {dx * ir, dy * ir, dz * ir};
        float* Ff = ws + F_OFF;
#pragma unroll
        for (int i = 0; i < 8; i++) {
            float gsi = f[src * 32 + i];
            float g0 = f[src * 32 + 8 + 3 * i + 0];
            float g1 = f[src * 32 + 8 + 3 * i + 1];
            float g2 = f[src * 32 + 8 + 3 * i + 2];
            Ff[i * 24 + e] = gsi;
            Ff[(8 + i) * 24 + e] = fmaf(g0, uu[0], fmaf(g1, uu[1], g2 * uu[2]));
            Ff[(16 + i * 3 + 0) * 24 + e] = gsi * uu[0];
            Ff[(16 + i * 3 + 1) * 24 + e] = gsi * uu[1];
            Ff[(16 + i * 3 + 2) * 24 + e] = gsi * uu[2];
            Ff[(40 + i * 3 + 0) * 24 + e] = g0;
            Ff[(40 + i * 3 + 1) * 24 + e] = g1;
            Ff[(40 + i * 3 + 2) * 24 + e] = g2;
        }
        float rr = r * (11.0f / 3.5f);
#pragma unroll
        for (int b = 0; b < 10; b++) {
            float d = rr - (float)(b + 1);
            ws[EMB_OFF + b * 24 + e] = 26.66929f * ss(d + 1.f) * ss(1.f - d);
        }
        float x = 10.f * (1.f - r * (1.f / 3.5f));
        ws[LC_OFF + e] = (x > 0.f) ? -__fdividef(1.f, x) : -1e30f;
    }
    stage(sm, Wk2, Wk1, tid);
    __syncthreads();

    // ============ PASS 0: k-net -> logits -> coef ============
    if (active) {
        u64 qq[4], qv[3][4];
        {
            const u64* qsp = (const u64*)(g_qt + n * 32);
#pragma unroll
            for (int m = 0; m < 4; m++) qq[m] = qsp[m];
            const float* qf = g_qt + n * 32 + 8;
#pragma unroll
            for (int c = 0; c < 3; c++)
#pragma unroll
                for (int m = 0; m < 4; m++)
                    qv[c][m] = pk2(qf[(2 * m) * 3 + c], qf[(2 * m + 1) * 3 + c]);
        }
        u64 Lacc[10];
#pragma unroll
        for (int m = 0; m < 10; m++) Lacc[m] = 0ULL;

#pragma unroll 1
        for (int half = 0; half < 2; half++) {
            int t = half * 32 + lane;
            u64 h[10], D[10];
            fc1_row(ws, W1s, t, h);
#pragma unroll
            for (int m = 0; m < 10; m++) D[m] = 0ULL;
            const u64* wrow = W2s64 + t * 129;
#pragma unroll 1
            for (int pi = 0; pi < 16; pi++)  // paths 0,1 (xi = pi)
                dupd(ws, pi, dot8(wrow + pi * 4, qq), D);
#pragma unroll 1
            for (int pi = 0; pi < 16; pi++) {  // paths 2,3
                const u64* wk = wrow + 64 + pi * 4;
                int xb = 16 + (pi >> 3) * 24 + (pi & 7) * 3;
                float sc = (pi >= 8) ? 0.5773502691896258f : 1.0f;
#pragma unroll
                for (int c = 0; c < 3; c++)
                    dupd(ws, xb + c, dot8(wk, qv[c]) * sc, D);
            }
#pragma unroll
            for (int m = 0; m < 10; m++) Lacc[m] = f2(h[m], D[m], Lacc[m]);
        }
#pragma unroll
        for (int o = 16; o >= 1; o >>= 1)
#pragma unroll
            for (int m = 0; m < 10; m++)
                Lacc[m] = add2(Lacc[m], __shfl_xor_sync(0xffffffffu, Lacc[m], o));
        if (lane == 0) {
            u64* Lg = (u64*)(ws + LG_OFF);
#pragma unroll
            for (int m = 0; m < 10; m++) Lg[m] = Lacc[m];
        }
        __syncwarp();
        {
            float L = -3.0e38f;
            if (lane < 20)
                L = fmaf(0.022097086912079608f, ws[LG_OFF + lane], ws[LC_OFF + lane]);
            float M = L;
#pragma unroll
            for (int o = 16; o >= 1; o >>= 1)
                M = fmaxf(M, __shfl_xor_sync(0xffffffffu, M, o));
            float ex = (lane < 20) ? __expf(L - M) : 0.f;
            float z = bsum(ex);
            if (lane < 20)
                ws[CO_OFF + lane] = 0.25f * sqrtf(__fdividef(ex, z) + 1e-12f);
        }
        __syncwarp();
    }

    __syncthreads();
    stage(sm, Wv2, Wv1, tid);
    __syncthreads();

    // ============ PASS 1: v-net -> outputs ============
    if (active) {
        u64 co[10];
        {
            const u64* cp = (const u64*)(ws + CO_OFF);
#pragma unroll
            for (int m = 0; m < 10; m++) co[m] = cp[m];
        }
        u64 os[4] = {0ULL, 0ULL, 0ULL, 0ULL};
        u64 ov[3][4] = {};

#pragma unroll 1
        for (int half = 0; half < 2; half++) {
            int t = half * 32 + lane;
            u64 h[10];
            fc1_row(ws, W1s, t, h);
#pragma unroll
            for (int m = 0; m < 10; m++) h[m] = mul2(h[m], co[m]);
            const u64* wrow = W2s64 + t * 129;
#pragma unroll 1
            for (int pi = 0; pi < 16; pi++) {  // paths 0,1 -> out_s
                float S = srow(ws, pi, h);
                u64 Sd = pk2(S, S);
                const u64* wk = wrow + pi * 4;
#pragma unroll
                for (int r = 0; r < 4; r++) os[r] = f2(Sd, wk[r], os[r]);
            }
#pragma unroll 1
            for (int pi = 0; pi < 16; pi++) {  // paths 2,3 -> out_v
                const u64* wk = wrow + 64 + pi * 4;
                int xb = 16 + (pi >> 3) * 24 + (pi & 7) * 3;
                float sc = (pi < 8) ? 1.7320508075688772f : 1.0f;
#pragma unroll
                for (int c = 0; c < 3; c++) {
                    float S = srow(ws, xb + c, h) * sc;
                    u64 Sd = pk2(S, S);
#pragma unroll
                    for (int r = 0; r < 4; r++) ov[c][r] = f2(Sd, wk[r], ov[c][r]);
                }
            }
        }
#pragma unroll
        for (int o = 16; o >= 1; o >>= 1) {
#pragma unroll
            for (int r = 0; r < 4; r++)
                os[r] = add2(os[r], __shfl_xor_sync(0xffffffffu, os[r], o));
#pragma unroll
            for (int c = 0; c < 3; c++)
#pragma unroll
                for (int r = 0; r < 4; r++)
                    ov[c][r] = add2(ov[c][r], __shfl_xor_sync(0xffffffffu, ov[c][r], o));
        }
        if (lane < 4) {
            float a, b;
            upk2(os[lane], a, b);
            out[n * 32 + 2 * lane] = a;
            out[n * 32 + 2 * lane + 1] = b;
        } else if (lane < 16) {
            int idx = lane - 4;
            int c = idx >> 2, r = idx & 3;
            float a, b;
            upk2(ov[c][r], a, b);
            out[n * 32 + 8 + (2 * r) * 3 + c] = a;
            out[n * 32 + 8 + (2 * r + 1) * 3 + c] = b;
        }
    }
}

extern "C" void kernel_launch(void* const* d_in, const int* in_sizes, int n_in,
                              void* d_out, int out_size) {
    const float* f    = (const float*)d_in[0];
    const float* pos  = (const float*)d_in[1];
    const float* Wq_s = (const float*)d_in[2];
    const float* Wq_v = (const float*)d_in[3];
    const float* Wk1  = (const float*)d_in[4];
    const float* Wk2  = (const float*)d_in[5];
    const float* Wv1  = (const float*)d_in[6];
    const float* Wv2  = (const float*)d_in[7];
    const float* Wd_s = (const float*)d_in[8];
    const float* Wd_v = (const float*)d_in[9];
    const int* esrc   = (const int*)d_in[10];
    float* out = (float*)d_out;

    cudaFuncSetAttribute(se3_main, cudaFuncAttributeMaxDynamicSharedMemorySize, SMEM_BYTES);
    k0_qt<<<64, 256>>>(f, Wq_s, Wq_v, Wd_s, Wd_v);
    se3_main<<<(NN + 11) / 12, 384, SMEM_BYTES>>>(f, pos, Wk1, Wk2, Wv1, Wv2, esrc, out);
}